// round 16
// baseline (speedup 1.0000x reference)
#include <cuda_runtime.h>
#include <math.h>

// Problem constants (fixed by the reference: B=8192, V=8, J=32)
constexpr int BB = 8192;
constexpr int VV = 8;
constexpr int JJ = 32;
constexpr int PAIRS = BB * VV;                        // 65536 (b,v) problems
constexpr int WARPS_PER_BLOCK = 4;                    // block=128: best measured scheduling
constexpr int PAIRS_PER_WARP = 4;                     // 8-lane segments (best measured)
constexpr int PAIRS_PER_BLOCK = WARPS_PER_BLOCK * PAIRS_PER_WARP;  // 16
constexpr int NBLOCKS = PAIRS / PAIRS_PER_BLOCK;      // 4096
constexpr int NWARPS = PAIRS / PAIRS_PER_WARP;        // 16384 ticket granularity
constexpr float SCALE_KPS = 0.1f;
constexpr float ALPHA = 0.1f;
constexpr float LOG2_TBETA = 5.979470570797252f;      // log2(100^0.9)
constexpr double FIX = 262144.0;                      // 2^18 fixed-point scale

__device__ unsigned long long g_accum = 0ull;         // fixed-point grid sum
__device__ unsigned int g_ticket = 0u;                // completion counter (per warp)

// single-MUFU approximate ops
__device__ __forceinline__ float frcp_fast(float x) {
    float r; asm("rcp.approx.f32 %0, %1;" : "=f"(r) : "f"(x)); return r;
}
__device__ __forceinline__ float fsqrt_fast(float x) {
    float r; asm("sqrt.approx.f32 %0, %1;" : "=f"(r) : "f"(x)); return r;
}
__device__ __forceinline__ float lg2_fast(float x) {
    float r; asm("lg2.approx.f32 %0, %1;" : "=f"(r) : "f"(x)); return r;
}
__device__ __forceinline__ float ex2_fast(float x) {
    float r; asm("ex2.approx.f32 %0, %1;" : "=f"(r) : "f"(x)); return r;
}

struct Acc { float pn2, in2, ls; };

__device__ __forceinline__ void do_joint(
    float X, float Y, float Z, float ix, float iy,
    const float4& c0, const float4& c1, const float4& c2,
    const float* __restrict__ kk, Acc& a)
{
    const float cx = c0.x * X + c0.y * Y + c0.z * Z + c0.w;
    const float cy = c1.x * X + c1.y * Y + c1.z * Z + c1.w;
    const float cz = c2.x * X + c2.y * Y + c2.z * Z + c2.w;
    const float px = kk[0] * cx + kk[1] * cy + kk[2] * cz;
    const float py = kk[3] * cx + kk[4] * cy + kk[5] * cz;
    const float pz = kk[6] * cx + kk[7] * cy + kk[8] * cz;
    const float iz = frcp_fast(pz);
    const float u = px * iz, w = py * iz;
    a.pn2 += u * u + w * w;
    a.in2 += ix * ix + iy * iy;
    float d0 = (u - ix) * SCALE_KPS; d0 = d0 * d0;
    float d1 = (w - iy) * SCALE_KPS; d1 = d1 * d1;
    // EXACT min-trick: where(d>100, T_BETA*d^0.1, d) == min(d, T_BETA*d^0.1)
    // (curves cross exactly at d=THRESHOLD); T_BETA folded into the exponent.
    const float e0 = ex2_fast(fmaf(lg2_fast(d0), ALPHA, LOG2_TBETA));
    const float e1 = ex2_fast(fmaf(lg2_fast(d1), ALPHA, LOG2_TBETA));
    a.ls += fminf(d0, e0) + fminf(d1, e1);
}

__global__ __launch_bounds__(WARPS_PER_BLOCK * 32, 12)  // 48 warps/SM theoretical
void qpl_fused(const float* __restrict__ Kmat,
               const float* __restrict__ cam,
               const float* __restrict__ kps,
               const float* __restrict__ init,
               float* __restrict__ out) {
    const int t = threadIdx.x;
    const int warp = t >> 5;
    const int lane = t & 31;
    const int grp = lane >> 3;      // which of 4 pairs in this warp
    const int sub = lane & 7;       // lane in 8-lane group; joints 4*sub..4*sub+3
    const int pair = blockIdx.x * PAIRS_PER_BLOCK + warp * PAIRS_PER_WARP + grp;
    const int b = pair >> 3;        // 4 consecutive pairs share one batch

    // ---- loads: 16B-aligned vectors / group-uniform broadcast ----
    const float4* ikp = reinterpret_cast<const float4*>(init) + (size_t)pair * 16 + sub * 2;
    const float4 ia = ikp[0], ib = ikp[1];
    const float4* kp4 = reinterpret_cast<const float4*>(kps + (size_t)b * (JJ * 3) + sub * 12);
    const float4 q0 = kp4[0], q1 = kp4[1], q2 = kp4[2];
    const float4* C = reinterpret_cast<const float4*>(cam + (size_t)pair * 12);
    const float4 c0 = C[0], c1 = C[1], c2 = C[2];
    const float* Kp = Kmat + (size_t)pair * 9;
    float kk[9];
#pragma unroll
    for (int i = 0; i < 9; i++) kk[i] = Kp[i];

    Acc a = {0.0f, 0.0f, 0.0f};
    // 4 independent joint chains -> ILP hides MUFU/LDG latency
    do_joint(q0.x, q0.y, q0.z, ia.x, ia.y, c0, c1, c2, kk, a);
    do_joint(q0.w, q1.x, q1.y, ia.z, ia.w, c0, c1, c2, kk, a);
    do_joint(q1.z, q1.w, q2.x, ib.x, ib.y, c0, c1, c2, kk, a);
    do_joint(q2.y, q2.z, q2.w, ib.z, ib.w, c0, c1, c2, kk, a);

    // ---- segmented butterfly reduce within each 8-lane group ----
#pragma unroll
    for (int o = 4; o; o >>= 1) {
        a.pn2 += __shfl_xor_sync(0xFFFFFFFFu, a.pn2, o);
        a.in2 += __shfl_xor_sync(0xFFFFFFFFu, a.in2, o);
        a.ls  += __shfl_xor_sync(0xFFFFFFFFu, a.ls,  o);
    }

    // ---- warp-autonomous epilogue: no smem, no __syncthreads ----
    // all lanes compute the per-pair loss (uniform within each 8-lane group);
    // zero it on non-leader lanes, then 2 shfl sum the 4 group results.
    const float penal = fabsf(fsqrt_fast(a.pn2 * frcp_fast(a.in2)) - 1.0f);
    float s = (sub == 0) ? (penal * a.ls * 0.5f) : 0.0f;
    s += __shfl_xor_sync(0xFFFFFFFFu, s, 8);
    s += __shfl_xor_sync(0xFFFFFFFFu, s, 16);

    if (lane == 0) {
        // order-invariant integer accumulation => deterministic grid sum
        const long long q = __double2ll_rn((double)s * FIX);
        atomicAdd(&g_accum, (unsigned long long)q);
        __threadfence();
        const unsigned int tk = atomicAdd(&g_ticket, 1u);
        if (tk == (unsigned int)(NWARPS - 1)) {
            const unsigned long long total = atomicAdd(&g_accum, 0ull);
            const double mean = ((double)(long long)total) / FIX / (double)PAIRS;
            out[0] = (float)mean;
            atomicExch(&g_accum, 0ull);
            __threadfence();
            atomicExch(&g_ticket, 0u);
        }
    }
}

extern "C" void kernel_launch(void* const* d_in, const int* in_sizes, int n_in,
                              void* d_out, int out_size) {
    const float* Kmat = (const float*)d_in[0];  // [B,V,3,3]
    const float* cam  = (const float*)d_in[1];  // [B,V,3,4]
    const float* kps  = (const float*)d_in[2];  // [B,J,3]
    const float* init = (const float*)d_in[3];  // [B,V,J,2]
    float* out = (float*)d_out;

    qpl_fused<<<NBLOCKS, WARPS_PER_BLOCK * 32>>>(Kmat, cam, kps, init, out);
}

// round 17
// speedup vs baseline: 1.4138x; 1.4138x over previous
#include <cuda_runtime.h>
#include <math.h>

// Problem constants (fixed by the reference: B=8192, V=8, J=32)
constexpr int BB = 8192;
constexpr int VV = 8;
constexpr int JJ = 32;
constexpr int PAIRS = BB * VV;                        // 65536 (b,v) problems
constexpr int WARPS_PER_BLOCK = 4;                    // block=128: best measured scheduling
constexpr int PAIRS_PER_WARP = 4;                     // 8-lane segments (best measured)
constexpr int PAIRS_PER_BLOCK = WARPS_PER_BLOCK * PAIRS_PER_WARP;  // 16
constexpr int NBLOCKS = PAIRS / PAIRS_PER_BLOCK;      // 4096: measured-safe atomic level
constexpr float SCALE_KPS = 0.1f;
constexpr float ALPHA = 0.1f;
constexpr float LOG2_TBETA = 5.979470570797252f;      // log2(100^0.9)
constexpr double FIX = 262144.0;                      // 2^18 fixed-point scale

__device__ unsigned long long g_accum = 0ull;         // fixed-point grid sum
__device__ unsigned int g_ticket = 0u;                // completion counter (per block)

// single-MUFU approximate ops
__device__ __forceinline__ float frcp_fast(float x) {
    float r; asm("rcp.approx.f32 %0, %1;" : "=f"(r) : "f"(x)); return r;
}
__device__ __forceinline__ float fsqrt_fast(float x) {
    float r; asm("sqrt.approx.f32 %0, %1;" : "=f"(r) : "f"(x)); return r;
}
__device__ __forceinline__ float lg2_fast(float x) {
    float r; asm("lg2.approx.f32 %0, %1;" : "=f"(r) : "f"(x)); return r;
}
__device__ __forceinline__ float ex2_fast(float x) {
    float r; asm("ex2.approx.f32 %0, %1;" : "=f"(r) : "f"(x)); return r;
}

struct Acc { float pn2, in2, ls; };

__device__ __forceinline__ void do_joint(
    float X, float Y, float Z, float ix, float iy,
    const float4& c0, const float4& c1, const float4& c2,
    const float* __restrict__ kk, Acc& a)
{
    const float cx = c0.x * X + c0.y * Y + c0.z * Z + c0.w;
    const float cy = c1.x * X + c1.y * Y + c1.z * Z + c1.w;
    const float cz = c2.x * X + c2.y * Y + c2.z * Z + c2.w;
    const float px = kk[0] * cx + kk[1] * cy + kk[2] * cz;
    const float py = kk[3] * cx + kk[4] * cy + kk[5] * cz;
    const float pz = kk[6] * cx + kk[7] * cy + kk[8] * cz;
    const float iz = frcp_fast(pz);
    const float u = px * iz, w = py * iz;
    a.pn2 += u * u + w * w;
    a.in2 += ix * ix + iy * iy;
    float d0 = (u - ix) * SCALE_KPS; d0 = d0 * d0;
    float d1 = (w - iy) * SCALE_KPS; d1 = d1 * d1;
    // EXACT min-trick: where(d>100, T_BETA*d^0.1, d) == min(d, T_BETA*d^0.1)
    // (curves cross exactly at d=THRESHOLD); T_BETA folded into the exponent.
    const float e0 = ex2_fast(fmaf(lg2_fast(d0), ALPHA, LOG2_TBETA));
    const float e1 = ex2_fast(fmaf(lg2_fast(d1), ALPHA, LOG2_TBETA));
    a.ls += fminf(d0, e0) + fminf(d1, e1);
}

__global__ __launch_bounds__(WARPS_PER_BLOCK * 32, 12)  // 48 warps/SM theoretical
void qpl_fused(const float* __restrict__ Kmat,
               const float* __restrict__ cam,
               const float* __restrict__ kps,
               const float* __restrict__ init,
               float* __restrict__ out) {
    const int t = threadIdx.x;
    const int warp = t >> 5;
    const int lane = t & 31;
    const int grp = lane >> 3;      // which of 4 pairs in this warp
    const int sub = lane & 7;       // lane in 8-lane group; joints 4*sub..4*sub+3
    const int pair = blockIdx.x * PAIRS_PER_BLOCK + warp * PAIRS_PER_WARP + grp;
    const int b = pair >> 3;        // 4 consecutive pairs share one batch

    // ---- loads: 16B-aligned vectors / group-uniform broadcast ----
    const float4* ikp = reinterpret_cast<const float4*>(init) + (size_t)pair * 16 + sub * 2;
    const float4 ia = ikp[0], ib = ikp[1];
    const float4* kp4 = reinterpret_cast<const float4*>(kps + (size_t)b * (JJ * 3) + sub * 12);
    const float4 q0 = kp4[0], q1 = kp4[1], q2 = kp4[2];
    const float4* C = reinterpret_cast<const float4*>(cam + (size_t)pair * 12);
    const float4 c0 = C[0], c1 = C[1], c2 = C[2];
    const float* Kp = Kmat + (size_t)pair * 9;
    float kk[9];
#pragma unroll
    for (int i = 0; i < 9; i++) kk[i] = Kp[i];

    Acc a = {0.0f, 0.0f, 0.0f};
    // 4 independent joint chains -> ILP hides MUFU/LDG latency
    do_joint(q0.x, q0.y, q0.z, ia.x, ia.y, c0, c1, c2, kk, a);
    do_joint(q0.w, q1.x, q1.y, ia.z, ia.w, c0, c1, c2, kk, a);
    do_joint(q1.z, q1.w, q2.x, ib.x, ib.y, c0, c1, c2, kk, a);
    do_joint(q2.y, q2.z, q2.w, ib.z, ib.w, c0, c1, c2, kk, a);

    // ---- segmented butterfly reduce within each 8-lane group ----
#pragma unroll
    for (int o = 4; o; o >>= 1) {
        a.pn2 += __shfl_xor_sync(0xFFFFFFFFu, a.pn2, o);
        a.in2 += __shfl_xor_sync(0xFFFFFFFFu, a.in2, o);
        a.ls  += __shfl_xor_sync(0xFFFFFFFFu, a.ls,  o);
    }

    // ---- warp combines its own 4 pairs (2 shfl), then ONE atomic per block ----
    const float penal = fabsf(fsqrt_fast(a.pn2 * frcp_fast(a.in2)) - 1.0f);
    float s = (sub == 0) ? (penal * a.ls * 0.5f) : 0.0f;
    s += __shfl_xor_sync(0xFFFFFFFFu, s, 8);
    s += __shfl_xor_sync(0xFFFFFFFFu, s, 16);

    __shared__ float sm[WARPS_PER_BLOCK];
    if (lane == 0) sm[warp] = s;
    __syncthreads();

    if (t == 0) {
        const float tot = sm[0] + sm[1] + sm[2] + sm[3];
        // order-invariant integer accumulation => deterministic grid sum
        const long long q = __double2ll_rn((double)tot * FIX);
        atomicAdd(&g_accum, (unsigned long long)q);
        __threadfence();
        const unsigned int tk = atomicAdd(&g_ticket, 1u);
        if (tk == (unsigned int)(NBLOCKS - 1)) {
            const unsigned long long total = atomicAdd(&g_accum, 0ull);
            const double mean = ((double)(long long)total) / FIX / (double)PAIRS;
            out[0] = (float)mean;
            atomicExch(&g_accum, 0ull);
            __threadfence();
            atomicExch(&g_ticket, 0u);
        }
    }
}

extern "C" void kernel_launch(void* const* d_in, const int* in_sizes, int n_in,
                              void* d_out, int out_size) {
    const float* Kmat = (const float*)d_in[0];  // [B,V,3,3]
    const float* cam  = (const float*)d_in[1];  // [B,V,3,4]
    const float* kps  = (const float*)d_in[2];  // [B,J,3]
    const float* init = (const float*)d_in[3];  // [B,V,J,2]
    float* out = (float*)d_out;

    qpl_fused<<<NBLOCKS, WARPS_PER_BLOCK * 32>>>(Kmat, cam, kps, init, out);
}